// round 8
// baseline (speedup 1.0000x reference)
#include <cuda_runtime.h>
#include <cuda_fp16.h>
#include <cstdint>

#define UNITS   128
#define GATES   512
#define IN_DIM  512
#define BATCH   128
#define SEQ     1024

// scratch (no allocation allowed -> device globals)
// g_xw layout: [t][b][pos] with pos = 4*(col&127) + (col>>7)  (gate-permuted)
__device__ float  g_xw[(size_t)SEQ * BATCH * GATES];
__device__ __half g_WTh[(size_t)GATES * IN_DIM];       // W^T: [gate][i]
__device__ __half g_Uh[(size_t)UNITS * GATES];         // U, permuted cols: [k][4u+q]

__device__ __forceinline__ float tanhfast(float x) {
    float y;
    asm("tanh.approx.f32 %0, %1;" : "=f"(y) : "f"(x));
    return y;
}

// coalesced W transpose (32x32 smem tile) fp32 -> fp16
__global__ __launch_bounds__(256) void conv_w(const float* __restrict__ W) {
    __shared__ float tile[32][33];
    const int bx = blockIdx.x * 32;   // j block
    const int by = blockIdx.y * 32;   // i block
    const int tx = threadIdx.x, ty4 = threadIdx.y;   // 32 x 8
    #pragma unroll
    for (int r = 0; r < 4; r++) {
        int ty = ty4 * 4 + r;
        tile[ty][tx] = W[(size_t)(by + ty) * GATES + bx + tx];
    }
    __syncthreads();
    #pragma unroll
    for (int r = 0; r < 4; r++) {
        int ty = ty4 * 4 + r;
        g_WTh[(size_t)(bx + ty) * IN_DIM + by + tx] = __float2half(tile[tx][ty]);
    }
}
// U conversion with gate-permuted column order: dst[k][4u+q] = U[k][128q+u]
__global__ void conv_u(const float* __restrict__ U) {
    int idx = blockIdx.x * 256 + threadIdx.x;          // 128*512
    int k = idx >> 9, j = idx & 511;
    g_Uh[(size_t)k * GATES + 4 * (j & 127) + (j >> 7)] = __float2half(U[idx]);
}

// ---------------- Phase A: xW GEMM (fp16 mma.sync + ldmatrix) ------------
#define BM 128
#define BN 128
#define BK 32
#define LDA 56          // halfs; 112B row stride: 16B-aligned, LDSM conflict-free
#define ABUF (BM * LDA) // halfs per buffer
#define GEMM_SMEM (4 * ABUF * 2 * (int)sizeof(__half))   // 2 arrays x 2 buffers

#define LDSM_X4(d0, d1, d2, d3, a)                                          \
    asm volatile("ldmatrix.sync.aligned.m8n8.x4.shared.b16 {%0,%1,%2,%3}, [%4];" \
                 : "=r"(d0), "=r"(d1), "=r"(d2), "=r"(d3) : "r"(a))

__global__ __launch_bounds__(256) void gemm_xw(const float* __restrict__ x,
                                               const float* __restrict__ bias) {
    extern __shared__ __align__(16) __half smh[];
    __half* As = smh;               // [2][BM][LDA]
    __half* Bs = smh + 2 * ABUF;    // [2][BN][LDA]

    const int tid = threadIdx.x;
    const int nb  = blockIdx.x;      // 0..3  gate-column block
    const int t   = blockIdx.y;      // 0..1023 timestep
    const int lane = tid & 31, wid = tid >> 5;
    const int wm = wid & 3, wn = wid >> 2;     // 4(m) x 2(n) warps
    const int g  = lane >> 2, tg2 = (lane & 3) * 2;

    float acc[2][8][4];
    #pragma unroll
    for (int a = 0; a < 2; a++)
        #pragma unroll
        for (int q = 0; q < 8; q++)
            #pragma unroll
            for (int c = 0; c < 4; c++) acc[a][q][c] = 0.f;

    const int ar = tid >> 3;               // A row (batch) 0..31 (+32*i)
    const int ak = (tid & 7) * 4;          // A k offset (halfs)
    const float* aptr = x + ((size_t)ar * SEQ + t) * IN_DIM + ak;
    const int bn_ = tid >> 1;              // B row (gate col)
    const int bk_ = (tid & 1) * 16;        // B k offset (halfs)
    const __half* bptr = g_WTh + (size_t)(nb * BN + bn_) * IN_DIM + bk_;

    // ldmatrix per-lane base addresses (shared space, bytes)
    const uint32_t sA = (uint32_t)__cvta_generic_to_shared(As);
    const uint32_t sB = (uint32_t)__cvta_generic_to_shared(Bs);
    const int ra  = (lane & 7) + ((lane >> 3) & 1) * 8;   // A row-in-tile
    const int alo = (lane >> 4) * 8;                      // A col half-offset
    const int rb  = ((lane >> 4) & 1) * 8 + (lane & 7);   // B row-in-tile
    const int blo = ((lane >> 3) & 1) * 8;                // B col half-offset
    const uint32_t aBase = sA + ((wm * 32 + ra) * LDA + alo) * 2;
    const uint32_t bBase = sB + ((wn * 64 + rb) * LDA + blo) * 2;

    float4 av[4];
    uint4  bv[2];

    auto ldg = [&](int kt) {
        const float* ap = aptr + kt * BK;
        #pragma unroll
        for (int i = 0; i < 4; i++)
            av[i] = *(const float4*)(ap + (size_t)i * 32 * SEQ * IN_DIM);
        const __half* bp = bptr + kt * BK;
        bv[0] = *(const uint4*)(bp);
        bv[1] = *(const uint4*)(bp + 8);
    };
    auto sts = [&](int buf) {
        #pragma unroll
        for (int i = 0; i < 4; i++) {
            __half2 h0 = __floats2half2_rn(av[i].x, av[i].y);
            __half2 h1 = __floats2half2_rn(av[i].z, av[i].w);
            uint2 u;
            u.x = *reinterpret_cast<unsigned*>(&h0);
            u.y = *reinterpret_cast<unsigned*>(&h1);
            *(uint2*)&As[(buf * BM + ar + 32 * i) * LDA + ak] = u;
        }
        *(uint4*)&Bs[(buf * BN + bn_) * LDA + bk_]     = bv[0];
        *(uint4*)&Bs[(buf * BN + bn_) * LDA + bk_ + 8] = bv[1];
    };

    ldg(0); sts(0); __syncthreads();

    #pragma unroll 1
    for (int kt = 0; kt < 16; kt++) {
        const int cur = kt & 1;
        if (kt < 15) ldg(kt + 1);

        const uint32_t aB = aBase + cur * (ABUF * 2);
        const uint32_t bB = bBase + cur * (ABUF * 2);

        #pragma unroll
        for (int ks = 0; ks < 2; ks++) {
            const int k0b = ks * 32;            // k0 halfs * 2 bytes
            uint32_t afr[2][4], bfr[8][2];
            #pragma unroll
            for (int mt = 0; mt < 2; mt++)
                LDSM_X4(afr[mt][0], afr[mt][1], afr[mt][2], afr[mt][3],
                        aB + mt * (16 * LDA * 2) + k0b);
            #pragma unroll
            for (int pr = 0; pr < 4; pr++)
                LDSM_X4(bfr[2*pr][0], bfr[2*pr][1], bfr[2*pr+1][0], bfr[2*pr+1][1],
                        bB + pr * (16 * LDA * 2) + k0b);
            #pragma unroll
            for (int mt = 0; mt < 2; mt++)
                #pragma unroll
                for (int nt = 0; nt < 8; nt++) {
                    float* c = acc[mt][nt];
                    asm volatile(
                        "mma.sync.aligned.m16n8k16.row.col.f32.f16.f16.f32 "
                        "{%0,%1,%2,%3}, {%4,%5,%6,%7}, {%8,%9}, {%0,%1,%2,%3};\n"
                        : "+f"(c[0]), "+f"(c[1]), "+f"(c[2]), "+f"(c[3])
                        : "r"(afr[mt][0]), "r"(afr[mt][1]), "r"(afr[mt][2]), "r"(afr[mt][3]),
                          "r"(bfr[nt][0]), "r"(bfr[nt][1]));
                }
        }
        if (kt < 15) { sts(1 - cur); __syncthreads(); }
    }

    // epilogue, gate-permuted store: pos(col) = 4*(col & 127) + nb
    #pragma unroll
    for (int mt = 0; mt < 2; mt++) {
        const int r0 = wm * 32 + mt * 16 + g;
        #pragma unroll
        for (int nt = 0; nt < 8; nt++) {
            const int col  = nb * BN + wn * 64 + nt * 8 + tg2;
            const int pos  = 4 * (col & 127) + nb;
            const float b0 = __ldg(&bias[col]), b1 = __ldg(&bias[col + 1]);
            float* row0 = &g_xw[((size_t)t * BATCH + r0    ) * GATES];
            float* row1 = &g_xw[((size_t)t * BATCH + r0 + 8) * GATES];
            row0[pos]     = acc[mt][nt][0] + b0;
            row0[pos + 4] = acc[mt][nt][1] + b1;
            row1[pos]     = acc[mt][nt][2] + b0;
            row1[pos + 4] = acc[mt][nt][3] + b1;
        }
    }
}

// ---------------- Phase B: recurrence, U register-resident, 1024 thr -----
// Phase 1 (all 32 warps): thread (kg = tid>>7, cg = tid&127) owns permuted
// gate cols [4cg,4cg+4) over k-chunk [16kg,16kg+16); partials -> pbuf.
// Phase 2 (warps 0-15, 4/SMSP): thread 4u+q computes gate q of unit u
// (8 conflict-free LDS + tanh), shfl to q=0 lane for the cell update.

__global__ __launch_bounds__(1024) void lstm_rec(float* __restrict__ out) {
    __shared__ __align__(16) __half2 hsp[UNITS];     // splatted (h_k, h_k)
    __shared__ __align__(16) float pbuf[8][GATES];   // k-split partials, permuted

    const int tid = threadIdx.x;
    const int kg  = tid >> 7;        // 0..7
    const int cg  = tid & 127;       // 0..127
    const int b   = blockIdx.x;
    const int lane = tid & 31;

    // U slice -> registers (32 half2 = 4 permuted cols x 16 k), one-time
    __half2 ureg[16][2];
    {
        const __half* ub = g_Uh + (size_t)(kg * 16) * GATES + cg * 4;
        #pragma unroll
        for (int k = 0; k < 16; k++)
            *(uint2*)&ureg[k][0] = *(const uint2*)(ub + (size_t)k * GATES);
    }
    if (tid < UNITS) hsp[tid] = __float2half2_rn(0.f);
    float c = 0.f, hlast = 0.f;
    __syncthreads();

    // xW prefetch: thread tid<512 reads permuted gate 'tid' of batch b
    const float* xwp = g_xw + (size_t)b * GATES + tid;
    float xw = 0.f;
    if (tid < 512) { xw = *xwp; }
    xwp += (size_t)BATCH * GATES;

    const __half2 z2 = __float2half2_rn(0.f);

    for (int step = 0; step < SEQ; step++) {
        // ---- phase 1: matvec partial over k-chunk of 16
        float2 f0 = make_float2(0.f, 0.f), f1 = make_float2(0.f, 0.f);
        const uint4* h4 = (const uint4*)hsp + kg * 4;   // 16 k = 4 uint4
        #pragma unroll
        for (int e = 0; e < 4; e++) {
            union { uint4 v; __half2 h[4]; } hv;
            hv.v = h4[e];                                // broadcast LDS.128
            __half2 a0 = z2, a1 = z2;
            #pragma unroll
            for (int j = 0; j < 4; j++) {
                a0 = __hfma2(hv.h[j], ureg[e * 4 + j][0], a0);
                a1 = __hfma2(hv.h[j], ureg[e * 4 + j][1], a1);
            }
            float2 t0 = __half22float2(a0);              // fp32 flush every 4 k
            float2 t1 = __half22float2(a1);
            f0.x += t0.x; f0.y += t0.y;
            f1.x += t1.x; f1.y += t1.y;
        }
        *(float4*)&pbuf[kg][cg * 4] = make_float4(f0.x, f0.y, f1.x, f1.y);
        __syncthreads();

        // ---- phase 2: per-gate reduce + tanh, shfl-combine, cell update
        if (tid < 512) {
            float s = xw;
            #pragma unroll
            for (int k = 0; k < 8; k++) s += pbuf[k][tid];   // lane-consecutive
            const float z = tanhfast(s);
            if (step + 1 < SEQ) xw = *xwp;
            const int base = lane & ~3;
            const float zf = __shfl_sync(0xffffffffu, z, base + 1);
            const float zg = __shfl_sync(0xffffffffu, z, base + 2);
            const float zo = __shfl_sync(0xffffffffu, z, base + 3);
            if ((tid & 3) == 0) {                            // q==0 lane: unit u
                c = zf * c + z * zg;
                hlast = zo * tanhfast(c);
                hsp[tid >> 2] = __float2half2_rn(hlast);
            }
        }
        xwp += (size_t)BATCH * GATES;
        __syncthreads();
    }
    if (tid < 512 && (tid & 3) == 0) out[(size_t)b * UNITS + (tid >> 2)] = hlast;
}

// ---------------- launch -------------------------------------------------
extern "C" void kernel_launch(void* const* d_in, const int* in_sizes, int n_in,
                              void* d_out, int out_size) {
    const float* x = (const float*)d_in[0];
    const float* W = (const float*)d_in[1];
    const float* U = (const float*)d_in[2];
    const float* b = (const float*)d_in[3];
    float* out = (float*)d_out;

    cudaFuncSetAttribute(gemm_xw, cudaFuncAttributeMaxDynamicSharedMemorySize, GEMM_SMEM);

    conv_w<<<dim3(16, 16), dim3(32, 8)>>>(W);
    conv_u<<<(UNITS * GATES) / 256, 256>>>(U);
    gemm_xw<<<dim3(4, SEQ), 256, GEMM_SMEM>>>(x, b);
    lstm_rec<<<BATCH, 1024>>>(out);
}

// round 9
// speedup vs baseline: 1.2154x; 1.2154x over previous
#include <cuda_runtime.h>
#include <cuda_fp16.h>
#include <cstdint>

#define UNITS   128
#define GATES   512
#define IN_DIM  512
#define BATCH   128
#define SEQ     1024

// scratch (no allocation allowed -> device globals)
// g_xw layout: [t][b][pos] with pos = 4*(col&127) + (col>>7)  (gate-permuted)
__device__ float  g_xw[(size_t)SEQ * BATCH * GATES];
__device__ __half g_xh[(size_t)SEQ * BATCH * IN_DIM];  // x fp16, [t][b][i]
__device__ __half g_WTh[(size_t)GATES * IN_DIM];       // W^T: [gate][i]
__device__ __half g_Uh[(size_t)UNITS * GATES];         // U:   [k][j] (unpermuted)

__device__ __forceinline__ float tanhfast(float x) {
    float y;
    asm("tanh.approx.f32 %0, %1;" : "=f"(y) : "f"(x));
    return y;
}

// coalesced W transpose (32x32 smem tile) fp32 -> fp16
__global__ __launch_bounds__(256) void conv_w(const float* __restrict__ W) {
    __shared__ float tile[32][33];
    const int bx = blockIdx.x * 32;   // j block
    const int by = blockIdx.y * 32;   // i block
    const int tx = threadIdx.x, ty4 = threadIdx.y;   // 32 x 8
    #pragma unroll
    for (int r = 0; r < 4; r++) {
        int ty = ty4 * 4 + r;
        tile[ty][tx] = W[(size_t)(by + ty) * GATES + bx + tx];
    }
    __syncthreads();
    #pragma unroll
    for (int r = 0; r < 4; r++) {
        int ty = ty4 * 4 + r;
        g_WTh[(size_t)(bx + ty) * IN_DIM + by + tx] = __float2half(tile[tx][ty]);
    }
}
__global__ void conv_u(const float* __restrict__ U) {
    int idx = blockIdx.x * 256 + threadIdx.x;          // 128*512
    g_Uh[idx] = __float2half(U[idx]);
}
// x fp32 [b][t][i] -> fp16 [t][b][i]
__global__ __launch_bounds__(256) void conv_x(const float* __restrict__ x) {
    size_t gid = (size_t)blockIdx.x * 256 + threadIdx.x;   // over float4s
    int    i4  = (int)(gid & 127);
    size_t row = gid >> 7;                                 // b*SEQ + t
    int    tt  = (int)(row & (SEQ - 1));
    int    bb  = (int)(row >> 10);
    float4 v = *(const float4*)(x + row * IN_DIM + i4 * 4);
    __half2 h0 = __floats2half2_rn(v.x, v.y);
    __half2 h1 = __floats2half2_rn(v.z, v.w);
    uint2 u;
    u.x = *reinterpret_cast<unsigned*>(&h0);
    u.y = *reinterpret_cast<unsigned*>(&h1);
    *(uint2*)(g_xh + ((size_t)tt * BATCH + bb) * IN_DIM + i4 * 4) = u;
}

// ---------------- Phase A: xW GEMM (cp.async 3-buffer + mma.sync) --------
#define BM 128
#define BN 128
#define BK 32
#define LDA 40
#define TBUF (BM * LDA)                 // halfs per buffer per array
#define GEMM_SMEM (3 * 2 * TBUF * (int)sizeof(__half))   // 61440 B

__global__ __launch_bounds__(256, 2) void gemm_xw(const float* __restrict__ bias) {
    extern __shared__ __align__(16) __half smh[];
    __half* As = smh;                   // [3][BM][LDA]
    __half* Bs = smh + 3 * TBUF;        // [3][BN][LDA]

    const int tid = threadIdx.x;
    const int nb  = blockIdx.x;      // 0..3  gate-column block
    const int t   = blockIdx.y;      // 0..1023 timestep
    const int lane = tid & 31, wid = tid >> 5;
    const int wm = wid & 3, wn = wid >> 2;     // 4(m) x 2(n) warps
    const int g  = lane >> 2, tg2 = (lane & 3) * 2;

    float acc[2][8][4];
    #pragma unroll
    for (int a = 0; a < 2; a++)
        #pragma unroll
        for (int q = 0; q < 8; q++)
            #pragma unroll
            for (int c = 0; c < 4; c++) acc[a][q][c] = 0.f;

    const uint32_t sA = (uint32_t)__cvta_generic_to_shared(As);
    const uint32_t sB = (uint32_t)__cvta_generic_to_shared(Bs);

    // per-thread copy slots: 2 x 16B for A, 2 x 16B for B
    const int gi0 = tid * 2;
    const int row0 = gi0 >> 2, ch0 = gi0 & 3;
    const int row1 = (gi0 + 1) >> 2, ch1 = (gi0 + 1) & 3;
    const __half* gA = g_xh + (size_t)t * BATCH * IN_DIM;
    const __half* gB = g_WTh + (size_t)nb * BN * IN_DIM;

    auto issue = [&](int kt, int buf) {
        uint32_t da0 = sA + (uint32_t)(buf * TBUF + row0 * LDA + ch0 * 8) * 2;
        uint32_t da1 = sA + (uint32_t)(buf * TBUF + row1 * LDA + ch1 * 8) * 2;
        uint32_t db0 = sB + (uint32_t)(buf * TBUF + row0 * LDA + ch0 * 8) * 2;
        uint32_t db1 = sB + (uint32_t)(buf * TBUF + row1 * LDA + ch1 * 8) * 2;
        const __half* a0 = gA + (size_t)row0 * IN_DIM + kt * BK + ch0 * 8;
        const __half* a1 = gA + (size_t)row1 * IN_DIM + kt * BK + ch1 * 8;
        const __half* b0 = gB + (size_t)row0 * IN_DIM + kt * BK + ch0 * 8;
        const __half* b1 = gB + (size_t)row1 * IN_DIM + kt * BK + ch1 * 8;
        asm volatile("cp.async.ca.shared.global [%0], [%1], 16;" :: "r"(da0), "l"(a0));
        asm volatile("cp.async.ca.shared.global [%0], [%1], 16;" :: "r"(da1), "l"(a1));
        asm volatile("cp.async.ca.shared.global [%0], [%1], 16;" :: "r"(db0), "l"(b0));
        asm volatile("cp.async.ca.shared.global [%0], [%1], 16;" :: "r"(db1), "l"(b1));
    };

    issue(0, 0); asm volatile("cp.async.commit_group;" ::: "memory");
    issue(1, 1); asm volatile("cp.async.commit_group;" ::: "memory");
    issue(2, 2); asm volatile("cp.async.commit_group;" ::: "memory");

    #pragma unroll 1
    for (int kt = 0; kt < 16; kt++) {
        const int buf = kt % 3;
        asm volatile("cp.async.wait_group 2;" ::: "memory");
        __syncthreads();

        const __half* Ab = As + buf * TBUF;
        const __half* Bb = Bs + buf * TBUF;
        #pragma unroll
        for (int ks = 0; ks < 2; ks++) {
            const int k0 = ks * 16;
            uint32_t afr[2][4], bfr[8][2];
            #pragma unroll
            for (int mt = 0; mt < 2; mt++) {
                const int m0 = wm * 32 + mt * 16;
                afr[mt][0] = *(const uint32_t*)&Ab[(m0 + g    ) * LDA + k0 + tg2    ];
                afr[mt][1] = *(const uint32_t*)&Ab[(m0 + g + 8) * LDA + k0 + tg2    ];
                afr[mt][2] = *(const uint32_t*)&Ab[(m0 + g    ) * LDA + k0 + tg2 + 8];
                afr[mt][3] = *(const uint32_t*)&Ab[(m0 + g + 8) * LDA + k0 + tg2 + 8];
            }
            #pragma unroll
            for (int nt = 0; nt < 8; nt++) {
                const int n0 = wn * 64 + nt * 8 + g;
                bfr[nt][0] = *(const uint32_t*)&Bb[n0 * LDA + k0 + tg2    ];
                bfr[nt][1] = *(const uint32_t*)&Bb[n0 * LDA + k0 + tg2 + 8];
            }
            #pragma unroll
            for (int mt = 0; mt < 2; mt++)
                #pragma unroll
                for (int nt = 0; nt < 8; nt++) {
                    float* c = acc[mt][nt];
                    asm volatile(
                        "mma.sync.aligned.m16n8k16.row.col.f32.f16.f16.f32 "
                        "{%0,%1,%2,%3}, {%4,%5,%6,%7}, {%8,%9}, {%0,%1,%2,%3};\n"
                        : "+f"(c[0]), "+f"(c[1]), "+f"(c[2]), "+f"(c[3])
                        : "r"(afr[mt][0]), "r"(afr[mt][1]), "r"(afr[mt][2]), "r"(afr[mt][3]),
                          "r"(bfr[nt][0]), "r"(bfr[nt][1]));
                }
        }
        __syncthreads();
        if (kt + 3 < 16) issue(kt + 3, (kt + 3) % 3);
        asm volatile("cp.async.commit_group;" ::: "memory");   // keep group count uniform
    }

    // epilogue, gate-permuted store: pos(col) = 4*(col & 127) + nb
    #pragma unroll
    for (int mt = 0; mt < 2; mt++) {
        const int r0 = wm * 32 + mt * 16 + g;
        #pragma unroll
        for (int nt = 0; nt < 8; nt++) {
            const int col  = nb * BN + wn * 64 + nt * 8 + tg2;
            const int pos  = 4 * (col & 127) + nb;
            const float b0 = __ldg(&bias[col]), b1 = __ldg(&bias[col + 1]);
            float* row0 = &g_xw[((size_t)t * BATCH + r0    ) * GATES];
            float* row1 = &g_xw[((size_t)t * BATCH + r0 + 8) * GATES];
            row0[pos]     = acc[mt][nt][0] + b0;
            row0[pos + 4] = acc[mt][nt][1] + b1;
            row1[pos]     = acc[mt][nt][2] + b0;
            row1[pos + 4] = acc[mt][nt][3] + b1;
        }
    }
}

// ---------------- Phase B: recurrence, U register-resident, 1024 thr -----
// (round-6 structure; fp16 partial flush every 8 k instead of 4)

__global__ __launch_bounds__(1024) void lstm_rec(float* __restrict__ out) {
    __shared__ __align__(16) __half2 hsp[UNITS];     // splatted (h_k, h_k)
    __shared__ __align__(16) float pbuf[8][GATES];   // k-split partials (16KB)

    const int tid = threadIdx.x;
    const int kg  = tid >> 7;        // 0..7
    const int cg  = tid & 127;       // 0..127
    const int b   = blockIdx.x;

    // U slice -> registers (32 half2 = 4 cols x 16 k), one-time
    __half2 ureg[16][2];
    {
        const __half* ub = g_Uh + (size_t)(kg * 16) * GATES + cg * 4;
        #pragma unroll
        for (int k = 0; k < 16; k++)
            *(uint2*)&ureg[k][0] = *(const uint2*)(ub + (size_t)k * GATES);
    }
    if (tid < UNITS) hsp[tid] = __float2half2_rn(0.f);
    float c = 0.f, hlast = 0.f;
    __syncthreads();

    // xW prefetch: threads<128 read their unit's 4 permuted gates as float4
    const float* xwp = g_xw + (size_t)b * GATES + 4 * tid;
    float4 xw = make_float4(0.f, 0.f, 0.f, 0.f);
    if (tid < UNITS) xw = *(const float4*)xwp;
    xwp += (size_t)BATCH * GATES;

    const __half2 z2 = __float2half2_rn(0.f);

    for (int step = 0; step < SEQ; step++) {
        // ---- matvec partial over k-chunk of 16 (fp16 accum, flush every 8 k)
        float2 f0 = make_float2(0.f, 0.f), f1 = make_float2(0.f, 0.f);
        const uint4* h4 = (const uint4*)hsp + kg * 4;   // 16 k = 4 uint4
        #pragma unroll
        for (int hf = 0; hf < 2; hf++) {
            __half2 a0 = z2, a1 = z2;
            #pragma unroll
            for (int e = 0; e < 2; e++) {
                union { uint4 v; __half2 h[4]; } hv;
                hv.v = h4[hf * 2 + e];                   // broadcast LDS.128
                #pragma unroll
                for (int j = 0; j < 4; j++) {
                    a0 = __hfma2(hv.h[j], ureg[(hf * 2 + e) * 4 + j][0], a0);
                    a1 = __hfma2(hv.h[j], ureg[(hf * 2 + e) * 4 + j][1], a1);
                }
            }
            float2 t0 = __half22float2(a0);
            float2 t1 = __half22float2(a1);
            f0.x += t0.x; f0.y += t0.y;
            f1.x += t1.x; f1.y += t1.y;
        }
        *(float4*)&pbuf[kg][cg * 4] = make_float4(f0.x, f0.y, f1.x, f1.y);
        __syncthreads();

        // ---- fused reduce + gates + cell (thread u owns unit u)
        if (tid < UNITS) {
            float z[4];
            #pragma unroll
            for (int q = 0; q < 4; q++) {
                float s = (&xw.x)[q];
                #pragma unroll
                for (int k = 0; k < 8; k++) s += pbuf[k][tid + 128 * q];
                z[q] = tanhfast(s);
            }
            c = z[1] * c + z[0] * z[2];
            hlast = z[3] * tanhfast(c);
            hsp[tid] = __float2half2_rn(hlast);
            if (step + 1 < SEQ) xw = *(const float4*)xwp;
            xwp += (size_t)BATCH * GATES;
        }
        __syncthreads();
    }
    if (tid < UNITS) out[(size_t)b * UNITS + tid] = hlast;
}

// ---------------- launch -------------------------------------------------
extern "C" void kernel_launch(void* const* d_in, const int* in_sizes, int n_in,
                              void* d_out, int out_size) {
    const float* x = (const float*)d_in[0];
    const float* W = (const float*)d_in[1];
    const float* U = (const float*)d_in[2];
    const float* b = (const float*)d_in[3];
    float* out = (float*)d_out;

    cudaFuncSetAttribute(gemm_xw, cudaFuncAttributeMaxDynamicSharedMemorySize, GEMM_SMEM);

    conv_w<<<dim3(16, 16), dim3(32, 8)>>>(W);
    conv_u<<<(UNITS * GATES) / 256, 256>>>(U);
    conv_x<<<(int)(((size_t)BATCH * SEQ * IN_DIM / 4) / 256), 256>>>(x);
    gemm_xw<<<dim3(4, SEQ), 256, GEMM_SMEM>>>(b);
    lstm_rec<<<BATCH, 1024>>>(out);
}

// round 10
// speedup vs baseline: 1.2323x; 1.0139x over previous
#include <cuda_runtime.h>
#include <cuda_fp16.h>
#include <cstdint>

#define UNITS   128
#define GATES   512
#define IN_DIM  512
#define BATCH   128
#define SEQ     1024

// scratch (no allocation allowed -> device globals)
// g_xw layout: [t][b][pos] with pos = 4*(col&127) + (col>>7)  (gate-permuted)
__device__ float  g_xw[(size_t)SEQ * BATCH * GATES];
__device__ __half g_xh[(size_t)SEQ * BATCH * IN_DIM];  // x fp16, [t][b][i]
__device__ __half g_WTh[(size_t)GATES * IN_DIM];       // W^T: [gate][i]
__device__ __half g_Uh[(size_t)UNITS * GATES];         // U:   [k][j]

__device__ __forceinline__ float tanhfast(float x) {
    float y;
    asm("tanh.approx.f32 %0, %1;" : "=f"(y) : "f"(x));
    return y;
}

// coalesced W transpose (32x32 smem tile) fp32 -> fp16
__global__ __launch_bounds__(256) void conv_w(const float* __restrict__ W) {
    __shared__ float tile[32][33];
    const int bx = blockIdx.x * 32;   // j block
    const int by = blockIdx.y * 32;   // i block
    const int tx = threadIdx.x, ty4 = threadIdx.y;   // 32 x 8
    #pragma unroll
    for (int r = 0; r < 4; r++) {
        int ty = ty4 * 4 + r;
        tile[ty][tx] = W[(size_t)(by + ty) * GATES + bx + tx];
    }
    __syncthreads();
    #pragma unroll
    for (int r = 0; r < 4; r++) {
        int ty = ty4 * 4 + r;
        g_WTh[(size_t)(bx + ty) * IN_DIM + by + tx] = __float2half(tile[tx][ty]);
    }
}
__global__ void conv_u(const float* __restrict__ U) {
    int idx = blockIdx.x * 256 + threadIdx.x;          // 128*512
    g_Uh[idx] = __float2half(U[idx]);
}
// x fp32 [b][t][i] -> fp16 [t][b][i]
__global__ __launch_bounds__(256) void conv_x(const float* __restrict__ x) {
    size_t gid = (size_t)blockIdx.x * 256 + threadIdx.x;   // over float4s
    int    i4  = (int)(gid & 127);
    size_t row = gid >> 7;                                 // b*SEQ + t
    int    tt  = (int)(row & (SEQ - 1));
    int    bb  = (int)(row >> 10);
    float4 v = *(const float4*)(x + row * IN_DIM + i4 * 4);
    __half2 h0 = __floats2half2_rn(v.x, v.y);
    __half2 h1 = __floats2half2_rn(v.z, v.w);
    uint2 u;
    u.x = *reinterpret_cast<unsigned*>(&h0);
    u.y = *reinterpret_cast<unsigned*>(&h1);
    *(uint2*)(g_xh + ((size_t)tt * BATCH + bb) * IN_DIM + i4 * 4) = u;
}

// ---------------- Phase A: xW GEMM (512 thr, 4-buffer cp.async) ----------
#define BM 128
#define BN 128
#define BK 32
#define LDA 40
#define TBUF (BM * LDA)                 // 5120 halfs per buffer per array
#define GEMM_SMEM (4 * 2 * TBUF * (int)sizeof(__half))   // 81920 B

__global__ __launch_bounds__(512, 2) void gemm_xw(const float* __restrict__ bias) {
    extern __shared__ __align__(16) __half smh[];
    __half* As = smh;                   // [4][BM][LDA]
    __half* Bs = smh + 4 * TBUF;        // [4][BN][LDA]

    const int tid = threadIdx.x;
    const int nb  = blockIdx.x;      // 0..3  gate-column block
    const int t   = blockIdx.y;      // 0..1023 timestep
    const int lane = tid & 31, wid = tid >> 5;
    const int wm = wid & 3, wn = wid >> 2;     // 4(m) x 4(n) warps
    const int g  = lane >> 2, tg2 = (lane & 3) * 2;

    float acc[2][4][4];
    #pragma unroll
    for (int a = 0; a < 2; a++)
        #pragma unroll
        for (int q = 0; q < 4; q++)
            #pragma unroll
            for (int c = 0; c < 4; c++) acc[a][q][c] = 0.f;

    const uint32_t sA = (uint32_t)__cvta_generic_to_shared(As);
    const uint32_t sB = (uint32_t)__cvta_generic_to_shared(Bs);

    // one 16B chunk per thread per array: row 0..127, chunk 0..3
    const int crow = tid >> 2, cch = tid & 3;
    const __half* gA = g_xh + (size_t)t * BATCH * IN_DIM + (size_t)crow * IN_DIM + cch * 8;
    const __half* gB = g_WTh + ((size_t)nb * BN + crow) * IN_DIM + cch * 8;
    const uint32_t dA = sA + (uint32_t)(crow * LDA + cch * 8) * 2;
    const uint32_t dB = sB + (uint32_t)(crow * LDA + cch * 8) * 2;

    auto issue = [&](int kt, int buf) {
        asm volatile("cp.async.ca.shared.global [%0], [%1], 16;"
                     :: "r"(dA + buf * (TBUF * 2)), "l"(gA + kt * BK));
        asm volatile("cp.async.ca.shared.global [%0], [%1], 16;"
                     :: "r"(dB + buf * (TBUF * 2)), "l"(gB + kt * BK));
    };

    issue(0, 0); asm volatile("cp.async.commit_group;" ::: "memory");
    issue(1, 1); asm volatile("cp.async.commit_group;" ::: "memory");
    issue(2, 2); asm volatile("cp.async.commit_group;" ::: "memory");

    #pragma unroll 1
    for (int kt = 0; kt < 16; kt++) {
        const int buf = kt & 3;
        asm volatile("cp.async.wait_group 2;" ::: "memory");
        __syncthreads();

        // issue next chunk into buffer (kt+3)&3 (last read at kt-1; barrier
        // above guarantees those reads are done)
        if (kt + 3 < 16) issue(kt + 3, (kt + 3) & 3);
        asm volatile("cp.async.commit_group;" ::: "memory");

        const __half* Ab = As + buf * TBUF;
        const __half* Bb = Bs + buf * TBUF;
        #pragma unroll
        for (int ks = 0; ks < 2; ks++) {
            const int k0 = ks * 16;
            uint32_t afr[2][4], bfr[4][2];
            #pragma unroll
            for (int mt = 0; mt < 2; mt++) {
                const int m0 = wm * 32 + mt * 16;
                afr[mt][0] = *(const uint32_t*)&Ab[(m0 + g    ) * LDA + k0 + tg2    ];
                afr[mt][1] = *(const uint32_t*)&Ab[(m0 + g + 8) * LDA + k0 + tg2    ];
                afr[mt][2] = *(const uint32_t*)&Ab[(m0 + g    ) * LDA + k0 + tg2 + 8];
                afr[mt][3] = *(const uint32_t*)&Ab[(m0 + g + 8) * LDA + k0 + tg2 + 8];
            }
            #pragma unroll
            for (int nt = 0; nt < 4; nt++) {
                const int n0 = wn * 32 + nt * 8 + g;
                bfr[nt][0] = *(const uint32_t*)&Bb[n0 * LDA + k0 + tg2    ];
                bfr[nt][1] = *(const uint32_t*)&Bb[n0 * LDA + k0 + tg2 + 8];
            }
            #pragma unroll
            for (int mt = 0; mt < 2; mt++)
                #pragma unroll
                for (int nt = 0; nt < 4; nt++) {
                    float* c = acc[mt][nt];
                    asm volatile(
                        "mma.sync.aligned.m16n8k16.row.col.f32.f16.f16.f32 "
                        "{%0,%1,%2,%3}, {%4,%5,%6,%7}, {%8,%9}, {%0,%1,%2,%3};\n"
                        : "+f"(c[0]), "+f"(c[1]), "+f"(c[2]), "+f"(c[3])
                        : "r"(afr[mt][0]), "r"(afr[mt][1]), "r"(afr[mt][2]), "r"(afr[mt][3]),
                          "r"(bfr[nt][0]), "r"(bfr[nt][1]));
                }
        }
    }

    // epilogue, gate-permuted store: pos(col) = 4*(col & 127) + nb
    #pragma unroll
    for (int mt = 0; mt < 2; mt++) {
        const int r0 = wm * 32 + mt * 16 + g;
        #pragma unroll
        for (int nt = 0; nt < 4; nt++) {
            const int col  = nb * BN + wn * 32 + nt * 8 + tg2;
            const int pos  = 4 * (col & 127) + nb;
            const float b0 = __ldg(&bias[col]), b1 = __ldg(&bias[col + 1]);
            float* row0 = &g_xw[((size_t)t * BATCH + r0    ) * GATES];
            float* row1 = &g_xw[((size_t)t * BATCH + r0 + 8) * GATES];
            row0[pos]     = acc[mt][nt][0] + b0;
            row0[pos + 4] = acc[mt][nt][1] + b1;
            row1[pos]     = acc[mt][nt][2] + b0;
            row1[pos + 4] = acc[mt][nt][3] + b1;
        }
    }
}

// ---------------- Phase B: recurrence, U register-resident, 1024 thr -----
__global__ __launch_bounds__(1024) void lstm_rec(float* __restrict__ out) {
    __shared__ __align__(16) __half2 hsp[UNITS];     // splatted (h_k, h_k)
    __shared__ __align__(16) float pbuf[8][GATES];   // k-split partials (16KB)

    const int tid = threadIdx.x;
    const int kg  = tid >> 7;        // 0..7
    const int cg  = tid & 127;       // 0..127
    const int b   = blockIdx.x;

    __half2 ureg[16][2];
    {
        const __half* ub = g_Uh + (size_t)(kg * 16) * GATES + cg * 4;
        #pragma unroll
        for (int k = 0; k < 16; k++)
            *(uint2*)&ureg[k][0] = *(const uint2*)(ub + (size_t)k * GATES);
    }
    if (tid < UNITS) hsp[tid] = __float2half2_rn(0.f);
    float c = 0.f, hlast = 0.f;
    __syncthreads();

    const float* xwp = g_xw + (size_t)b * GATES + 4 * tid;
    float4 xw = make_float4(0.f, 0.f, 0.f, 0.f);
    if (tid < UNITS) xw = *(const float4*)xwp;
    xwp += (size_t)BATCH * GATES;

    const __half2 z2 = __float2half2_rn(0.f);

    for (int step = 0; step < SEQ; step++) {
        float2 f0 = make_float2(0.f, 0.f), f1 = make_float2(0.f, 0.f);
        const uint4* h4 = (const uint4*)hsp + kg * 4;
        #pragma unroll
        for (int hf = 0; hf < 2; hf++) {
            __half2 a0 = z2, a1 = z2;
            #pragma unroll
            for (int e = 0; e < 2; e++) {
                union { uint4 v; __half2 h[4]; } hv;
                hv.v = h4[hf * 2 + e];
                #pragma unroll
                for (int j = 0; j < 4; j++) {
                    a0 = __hfma2(hv.h[j], ureg[(hf * 2 + e) * 4 + j][0], a0);
                    a1 = __hfma2(hv.h[j], ureg[(hf * 2 + e) * 4 + j][1], a1);
                }
            }
            float2 t0 = __half22float2(a0);
            float2 t1 = __half22float2(a1);
            f0.x += t0.x; f0.y += t0.y;
            f1.x += t1.x; f1.y += t1.y;
        }
        *(float4*)&pbuf[kg][cg * 4] = make_float4(f0.x, f0.y, f1.x, f1.y);
        __syncthreads();

        if (tid < UNITS) {
            float z[4];
            #pragma unroll
            for (int q = 0; q < 4; q++) {
                float s = (&xw.x)[q];
                #pragma unroll
                for (int k = 0; k < 8; k++) s += pbuf[k][tid + 128 * q];
                z[q] = tanhfast(s);
            }
            c = z[1] * c + z[0] * z[2];
            hlast = z[3] * tanhfast(c);
            hsp[tid] = __float2half2_rn(hlast);
            if (step + 1 < SEQ) xw = *(const float4*)xwp;
            xwp += (size_t)BATCH * GATES;
        }
        __syncthreads();
    }
    if (tid < UNITS) out[(size_t)b * UNITS + tid] = hlast;
}

// ---------------- launch -------------------------------------------------
extern "C" void kernel_launch(void* const* d_in, const int* in_sizes, int n_in,
                              void* d_out, int out_size) {
    const float* x = (const float*)d_in[0];
    const float* W = (const float*)d_in[1];
    const float* U = (const float*)d_in[2];
    const float* b = (const float*)d_in[3];
    float* out = (float*)d_out;

    cudaFuncSetAttribute(gemm_xw, cudaFuncAttributeMaxDynamicSharedMemorySize, GEMM_SMEM);

    conv_w<<<dim3(16, 16), dim3(32, 8)>>>(W);
    conv_u<<<(UNITS * GATES) / 256, 256>>>(U);
    conv_x<<<(int)(((size_t)BATCH * SEQ * IN_DIM / 4) / 256), 256>>>(x);
    gemm_xw<<<dim3(4, SEQ), 512, GEMM_SMEM>>>(b);
    lstm_rec<<<BATCH, 1024>>>(out);
}